// round 15
// baseline (speedup 1.0000x reference)
#include <cuda_runtime.h>
#include <cuda_fp16.h>
#include <math.h>
#include <math_constants.h>
#include <stdint.h>

#define NT 4096
#define DM 1024
#define DF 2048
#define NE 8
#define MAXROWS (2*NT)
#define MAXTILES 80
#define TILEY 72
#define W2TILES (NE * 64 * 32)          // 16384 32x32 tiles of w2
#define W2Y (W2TILES / 16)              // extra blockIdx.y rows on FFN1 grid

// ---------------- static device scratch ----------------
__device__ int   g_counts[NE];
__device__ float g_rowgate[MAXROWS];
__device__ int   g_perm[MAXROWS];
__device__ int   g_topidx[MAXROWS];
__device__ float g_gatesv[MAXROWS];
__device__ float g_imp_part[NE*NT];
__device__ float g_load_part[NE*NT];
__device__ float g_impsum[NE];
__device__ float g_loadsum[NE];
__device__ int   g_tile_e[MAXTILES];
__device__ int   g_tile_r0[MAXTILES];
__device__ int   g_tile_r1[MAXTILES];
__device__ int   g_ntiles;
__device__ int   g_fin;
__device__ float g_wgT[NE*DM];                     // [e][k] transposed gate weights
__device__ float g_wnT[NE*DM];
__device__ __half g_Xrh[(size_t)NT * DM];          // 8 MB,  K-perm16 fp16 x
__device__ __half g_Hh[(size_t)MAXROWS * DF];      // 32 MB, K-perm16 fp16 H
__device__ __half g_w1th[(size_t)NE * DF * DM];    // 32 MB [E][N=DF][K=DM] perm16
__device__ __half g_w2th[(size_t)NE * DM * DF];    // 32 MB [E][N=DM][K=DF] perm16

// ---------------- helpers ----------------
__device__ __forceinline__ uint32_t smem_u32(const void* p) {
    uint32_t r;
    asm("{ .reg .u64 t; cvta.to.shared.u64 t, %1; cvt.u32.u64 %0, t; }" : "=r"(r) : "l"(p));
    return r;
}
// within each 16-group, memory order [0,1,8,9, 2,3,10,11, 4,5,12,13, 6,7,14,15]
__device__ __forceinline__ int permk16(int k) {
    int r = k & 15, m = r & 7, h = (r >> 3) & 1;
    return (k & ~15) + (m >> 1) * 4 + h * 2 + (m & 1);
}
__device__ __forceinline__ void mma_f16(float* c, uint32_t a0, uint32_t a1,
                                        uint32_t a2, uint32_t a3,
                                        uint32_t b0, uint32_t b1) {
    asm volatile("mma.sync.aligned.m16n8k16.row.col.f32.f16.f16.f32 "
        "{%0,%1,%2,%3}, {%4,%5,%6,%7}, {%8,%9}, {%0,%1,%2,%3};"
        : "+f"(c[0]), "+f"(c[1]), "+f"(c[2]), "+f"(c[3])
        : "r"(a0), "r"(a1), "r"(a2), "r"(a3), "r"(b0), "r"(b1));
}

// ---------------- reset + gate-weight transpose ----------------
__global__ void reset_kernel(const float* __restrict__ wg, const float* __restrict__ wn) {
    int j = blockIdx.x * 256 + threadIdx.x;      // 0..8191
    int e = j >> 10, k = j & 1023;
    g_wgT[j] = wg[k * NE + e];
    g_wnT[j] = wn[k * NE + e];
    if (blockIdx.x == 0 && threadIdx.x < NE) g_counts[threadIdx.x] = 0;
    if (blockIdx.x == 0 && threadIdx.x == NE) g_fin = 0;
}

// ---------------- gating: one warp per token; coalesced [e][k] weight reads ----------
__global__ void gating_kernel(const float* __restrict__ x,
                              const float* __restrict__ noise)
{
    int warp = (blockIdx.x * blockDim.x + threadIdx.x) >> 5;
    int lane = threadIdx.x & 31;
    if (warp >= NT) return;
    const int t = warp;

    float cg[NE], ng[NE];
    #pragma unroll
    for (int e = 0; e < NE; e++) { cg[e] = 0.f; ng[e] = 0.f; }

    const float* xr = x + (size_t)t * DM;
    __half* xo = g_Xrh + (size_t)t * DM;
    for (int k = lane; k < DM; k += 32) {
        float xv = xr[k];
        xo[permk16(k)] = __float2half_rn(xv);
        #pragma unroll
        for (int e = 0; e < NE; e++) {
            cg[e] = fmaf(xv, g_wgT[e * DM + k], cg[e]);
            ng[e] = fmaf(xv, g_wnT[e * DM + k], ng[e]);
        }
    }
    #pragma unroll
    for (int e = 0; e < NE; e++) {
        #pragma unroll
        for (int o = 16; o > 0; o >>= 1) {
            cg[e] += __shfl_xor_sync(0xFFFFFFFFu, cg[e], o);
            ng[e] += __shfl_xor_sync(0xFFFFFFFFu, ng[e], o);
        }
    }

    if (lane == 0) {
        float clean[NE], stdv[NE], noisy[NE];
        #pragma unroll
        for (int e = 0; e < NE; e++) {
            clean[e] = cg[e];
            float v = ng[e];
            float sp = fmaxf(v, 0.f) + log1pf(expf(-fabsf(v)));
            stdv[e]  = sp + 0.01f;
            noisy[e] = clean[e] + noise[(size_t)t * NE + e] * stdv[e];
        }
        int i0 = 0, i1 = -1;
        float v0 = -CUDART_INF_F, v1 = -CUDART_INF_F, v2 = -CUDART_INF_F;
        #pragma unroll
        for (int e = 0; e < NE; e++) if (noisy[e] > v0) { v0 = noisy[e]; i0 = e; }
        #pragma unroll
        for (int e = 0; e < NE; e++) if (e != i0 && noisy[e] > v1) { v1 = noisy[e]; i1 = e; }
        #pragma unroll
        for (int e = 0; e < NE; e++) if (e != i0 && e != i1 && noisy[e] > v2) v2 = noisy[e];

        float d = expf(v1 - v0);
        float g0 = 1.f / (1.f + d);
        float g1 = d / (1.f + d);

        g_topidx[2*t]   = i0;  g_topidx[2*t+1] = i1;
        g_gatesv[2*t]   = g0;  g_gatesv[2*t+1] = g1;
        atomicAdd(&g_counts[i0], 1);
        atomicAdd(&g_counts[i1], 1);

        #pragma unroll
        for (int e = 0; e < NE; e++) {
            bool is_in = noisy[e] > v2;
            float thr  = is_in ? v2 : v1;
            float p = normcdff((clean[e] - thr) / stdv[e]);
            g_load_part[e*NT + t] = p;
            g_imp_part[e*NT + t]  = (e == i0) ? g0 : ((e == i1) ? g1 : 0.f);
        }
    }
}

// ---------------- merged meta + scatter: one block of 256 ----------------
__global__ void scatter_meta_kernel() {
    __shared__ int soff[NE];
    __shared__ int scur[NE];
    const int tid = threadIdx.x;
    if (tid == 0) {
        int off = 0, nt = 0;
        for (int e = 0; e < NE; e++) {
            soff[e] = off;
            int c = g_counts[e];
            for (int r = 0; r < c; r += 128) {
                g_tile_e[nt]  = e;
                g_tile_r0[nt] = off + r;
                g_tile_r1[nt] = off + ((r + 128 < c) ? (r + 128) : c);
                nt++;
            }
            off += c;
        }
        g_ntiles = nt;
    }
    if (tid < NE) scur[tid] = 0;
    __syncthreads();
    for (int t = tid; t < NT; t += 256) {
        #pragma unroll
        for (int j = 0; j < 2; j++) {
            int e = g_topidx[2*t + j];
            int p = atomicAdd(&scur[e], 1);
            int row = soff[e] + p;
            g_perm[row]    = t;
            g_rowgate[row] = g_gatesv[2*t + j];
        }
    }
}

// ---------------- w1 transpose -> fp16 perm16 (standalone; FFN1 needs it) ----------
__global__ void transpose_w1_kernel(const float* __restrict__ W1) {
    __shared__ float t[32][33];
    const int e = blockIdx.z;
    const float* Wp = W1 + (size_t)e * DM * DF;
    __half* Wo = g_w1th + (size_t)e * DM * DF;
    const int n0 = blockIdx.x * 32;   // N = DF, 64 blocks
    const int k0 = blockIdx.y * 32;   // K = DM, 32 blocks
    int tx = threadIdx.x, ty = threadIdx.y;
    #pragma unroll
    for (int i = 0; i < 32; i += 8)
        t[ty + i][tx] = Wp[(size_t)(k0 + ty + i) * DF + n0 + tx];
    __syncthreads();
    #pragma unroll
    for (int i = 0; i < 32; i += 8)
        Wo[(size_t)(n0 + ty + i) * DM + permk16(k0 + tx)] = __float2half_rn(t[tx][ty + i]);
}

// ---------------- fp16 mma.sync grouped GEMM (R8-proven config) ----------------
// FFN1 additionally carries the w2 transpose as extra blockIdx.y rows (y >= TILEY):
// those blocks repack W2[e][K=2048][N=1024] -> g_w2th[e][n][K-perm16], overlapping
// the DRAM-bound transpose with the crossbar/MMA-bound GEMM. FFN2 (launched after
// FFN1 fully completes) then consumes g_w2th.
#define RSH 80
#define ASTH (128*RSH)
#define STFH (2*ASTH)
#define GEMM_SMEM (2 * STFH * 2)       // 81920 bytes

template<bool FFN1>
__global__ void __launch_bounds__(256, 2)
mma_ffn_kernel(const float* __restrict__ bias, float* __restrict__ out,
               const float* __restrict__ W2src)
{
    constexpr int KTOT = FFN1 ? DM : DF;
    constexpr int NTOT = FFN1 ? DF : DM;
    constexpr int NS   = KTOT / 64;

    extern __shared__ __half smh[];

    if (FFN1 && blockIdx.y >= TILEY) {
        // ---- w2 transpose tile ----
        float (*tb)[33] = (float(*)[33])smh;
        const int j = (blockIdx.y - TILEY) * 16 + blockIdx.x;   // 0..16383
        const int e = j >> 11;
        const int rem = j & 2047;
        const int kb = rem & 63;          // K = 2048 -> 64 blocks
        const int nb = rem >> 6;          // N = 1024 -> 32 blocks
        const int k0 = kb * 32, n0 = nb * 32;
        const float* Wp = W2src + (size_t)e * DF * DM;
        __half* Wo = g_w2th + (size_t)e * DF * DM;
        const int tx = threadIdx.x & 31, ty = threadIdx.x >> 5;  // 32 x 8
        #pragma unroll
        for (int i = 0; i < 32; i += 8)
            tb[ty + i][tx] = Wp[(size_t)(k0 + ty + i) * DM + n0 + tx];
        __syncthreads();
        #pragma unroll
        for (int i = 0; i < 32; i += 8)
            Wo[(size_t)(n0 + ty + i) * DF + permk16(k0 + tx)] = __float2half_rn(tb[tx][ty + i]);
        return;
    }

    int tile = blockIdx.y;
    if (tile >= g_ntiles) return;
    const int e  = g_tile_e[tile];
    const int r0 = g_tile_r0[tile];
    const int r1 = g_tile_r1[tile];
    const int n0 = blockIdx.x * 128;

    const __half* Abase = FFN1 ? g_Xrh : g_Hh;
    const __half* Wt    = FFN1 ? g_w1th : g_w2th;

    const uint32_t smb = smem_u32(smh);

    const int tid = threadIdx.x;
    const int wid = tid >> 5;
    const int lane = tid & 31;
    const int warp_m = wid >> 2;   // 0..1
    const int warp_n = wid & 3;    // 0..3
    const int lm = lane >> 2;      // 0..7
    const int lk = lane & 3;       // 0..3

    const __half* src[8]; uint32_t sz[8]; uint32_t dst[8];
    #pragma unroll
    for (int i = 0; i < 8; i++) {
        int idx = tid + i * 256;
        if (idx < 1024) {
            int row = idx >> 3, ch = idx & 7;
            int gr = r0 + row;
            bool v = gr < r1;
            size_t ar = FFN1 ? (v ? (size_t)g_perm[gr] : 0) : (v ? (size_t)gr : 0);
            src[i] = Abase + ar * KTOT + ch * 8;
            sz[i]  = v ? 16u : 0u;
            dst[i] = smb + (uint32_t)(row * RSH + ch * 8) * 2u;
        } else {
            int j = idx - 1024;
            int row = j >> 3, ch = j & 7;
            src[i] = Wt + ((size_t)e * NTOT + (size_t)(n0 + row)) * KTOT + ch * 8;
            sz[i]  = 16u;
            dst[i] = smb + (uint32_t)(ASTH + row * RSH + ch * 8) * 2u;
        }
    }

    float acc[4][4][4];
    #pragma unroll
    for (int a = 0; a < 4; a++)
        #pragma unroll
        for (int b = 0; b < 4; b++)
            #pragma unroll
            for (int c = 0; c < 4; c++) acc[a][b][c] = 0.f;

    #pragma unroll
    for (int i = 0; i < 8; i++)
        asm volatile("cp.async.cg.shared.global [%0], [%1], 16, %2;"
                     :: "r"(dst[i]), "l"(src[i]), "r"(sz[i]) : "memory");
    asm volatile("cp.async.commit_group;" ::: "memory");

    for (int s = 0; s < NS; s++) {
        asm volatile("cp.async.wait_group 0;" ::: "memory");
        __syncthreads();

        if (s + 1 < NS) {
            uint32_t so = (uint32_t)(((s + 1) & 1) * STFH * 2);
            int k0 = (s + 1) * 64;
            #pragma unroll
            for (int i = 0; i < 8; i++)
                asm volatile("cp.async.cg.shared.global [%0], [%1], 16, %2;"
                             :: "r"(dst[i] + so), "l"(src[i] + k0), "r"(sz[i]) : "memory");
            asm volatile("cp.async.commit_group;" ::: "memory");
        }

        const __half* A = smh + (s & 1) * STFH;
        const __half* B = A + ASTH;

        #pragma unroll
        for (int kk = 0; kk < 4; kk++) {
            const int ko = kk * 16 + lk * 4;
            uint32_t af[4][4], bf[4][2];
            #pragma unroll
            for (int mt = 0; mt < 4; mt++) {
                int r = warp_m * 64 + mt * 16 + lm;
                uint2 p0 = *(const uint2*)(A + r * RSH + ko);
                uint2 p1 = *(const uint2*)(A + (r + 8) * RSH + ko);
                af[mt][0] = p0.x; af[mt][2] = p0.y;
                af[mt][1] = p1.x; af[mt][3] = p1.y;
            }
            #pragma unroll
            for (int nt = 0; nt < 4; nt++) {
                int c = warp_n * 32 + nt * 8 + lm;
                uint2 pb = *(const uint2*)(B + c * RSH + ko);
                bf[nt][0] = pb.x; bf[nt][1] = pb.y;
            }
            #pragma unroll
            for (int mt = 0; mt < 4; mt++)
                #pragma unroll
                for (int nt = 0; nt < 4; nt++)
                    mma_f16(acc[mt][nt], af[mt][0], af[mt][1], af[mt][2], af[mt][3],
                            bf[nt][0], bf[nt][1]);
        }
    }

    // ---- epilogue ----
    #pragma unroll
    for (int mt = 0; mt < 4; mt++) {
        #pragma unroll
        for (int nt = 0; nt < 4; nt++) {
            int c0 = n0 + warp_n * 32 + nt * 8 + 2 * lk;   // even
            float b0 = bias[(size_t)e * NTOT + c0];
            float b1 = bias[(size_t)e * NTOT + c0 + 1];
            #pragma unroll
            for (int h = 0; h < 2; h++) {
                int row = warp_m * 64 + mt * 16 + lm + h * 8;
                int gr = r0 + row;
                if (gr >= r1) continue;
                float v0 = acc[mt][nt][2*h + 0] + b0;
                float v1 = acc[mt][nt][2*h + 1] + b1;
                if (FFN1) {
                    int m = c0 & 7, hb = (c0 >> 3) & 1;
                    int pos = (c0 & ~15) + (m >> 1) * 4 + hb * 2;
                    __half2 hv = __floats2half2_rn(fmaxf(v0, 0.f), fmaxf(v1, 0.f));
                    *(__half2*)(g_Hh + (size_t)gr * DF + pos) = hv;
                } else {
                    float gate = g_rowgate[gr];
                    float* o = out + (size_t)g_perm[gr] * DM;
                    atomicAdd(o + c0,     v0 * gate);
                    atomicAdd(o + c0 + 1, v1 * gate);
                }
            }
        }
    }
}

// ---------------- finish: eps fixup + loss reduction + loss (fused) ----------------
__global__ void finish_kernel(float* __restrict__ out, int out_size) {
    int idx = blockIdx.x * blockDim.x + threadIdx.x;
    float v = out[idx];
    if (v == 0.0f) out[idx] = 2.2204460492503131e-16f;

    if (blockIdx.x < NE) {
        const int e = blockIdx.x;
        __shared__ float sl[256], si[256];
        float a = 0.f, b = 0.f;
        for (int i = threadIdx.x; i < NT; i += 256) {
            a += g_load_part[e*NT + i];
            b += g_imp_part[e*NT + i];
        }
        sl[threadIdx.x] = a; si[threadIdx.x] = b;
        __syncthreads();
        for (int s = 128; s > 0; s >>= 1) {
            if (threadIdx.x < s) {
                sl[threadIdx.x] += sl[threadIdx.x + s];
                si[threadIdx.x] += si[threadIdx.x + s];
            }
            __syncthreads();
        }
        if (threadIdx.x == 0) {
            g_loadsum[e] = sl[0];
            g_impsum[e]  = si[0];
            __threadfence();
            if (atomicAdd(&g_fin, 1) == NE - 1) {
                __threadfence();
                float mi = 0.f, ml = 0.f;
                for (int k = 0; k < NE; k++) { mi += g_impsum[k]; ml += g_loadsum[k]; }
                mi *= (1.f / NE); ml *= (1.f / NE);
                float vi = 0.f, vl = 0.f;
                for (int k = 0; k < NE; k++) {
                    float di = g_impsum[k] - mi; vi += di * di;
                    float dl = g_loadsum[k] - ml; vl += dl * dl;
                }
                vi /= (float)(NE - 1);
                vl /= (float)(NE - 1);
                out[out_size - 1] = 0.1f * (vi / (mi*mi + 1e-10f) + vl / (ml*ml + 1e-10f));
            }
        }
    }
}

// ---------------- launch ----------------
extern "C" void kernel_launch(void* const* d_in, const int* in_sizes, int n_in,
                              void* d_out, int out_size) {
    const float* x     = (const float*)d_in[0];
    const float* noise = (const float*)d_in[1];
    const float* wg    = (const float*)d_in[2];
    const float* wn    = (const float*)d_in[3];
    const float* w1    = (const float*)d_in[4];
    const float* b1    = (const float*)d_in[5];
    const float* w2    = (const float*)d_in[6];
    const float* b2    = (const float*)d_in[7];
    float* out = (float*)d_out;

    cudaFuncSetAttribute(mma_ffn_kernel<true>,
                         cudaFuncAttributeMaxDynamicSharedMemorySize, GEMM_SMEM);
    cudaFuncSetAttribute(mma_ffn_kernel<false>,
                         cudaFuncAttributeMaxDynamicSharedMemorySize, GEMM_SMEM);

    cudaMemsetAsync(out, 0, (size_t)out_size * sizeof(float));
    reset_kernel<<<32, 256>>>(wg, wn);
    gating_kernel<<<NT/4, 128>>>(x, noise);
    scatter_meta_kernel<<<1, 256>>>();

    transpose_w1_kernel<<<dim3(64, 32, NE), dim3(32, 8)>>>(w1);

    // FFN1 GEMM (y < TILEY) + w2 transpose (y >= TILEY) in one launch
    mma_ffn_kernel<true ><<<dim3(16, TILEY + W2Y), 256, GEMM_SMEM>>>(b1, nullptr, w2);
    mma_ffn_kernel<false><<<dim3(DM/128, TILEY), 256, GEMM_SMEM>>>(b2, out, nullptr);

    finish_kernel<<<(NT*DM)/256, 256>>>(out, out_size);
}

// round 16
// speedup vs baseline: 1.0568x; 1.0568x over previous
#include <cuda_runtime.h>
#include <cuda_fp16.h>
#include <math.h>
#include <math_constants.h>
#include <stdint.h>

#define NT 4096
#define DM 1024
#define DF 2048
#define NE 8
#define MAXROWS (2*NT)
#define MAXTILES 80
#define TILEY 72
#define W2TILES (NE * 64 * 32)          // 16384 32x32 tiles of w2
#define FFN1_BLOCKS (16 * TILEY)        // 1152

// ---------------- static device scratch ----------------
__device__ int   g_counts[NE];
__device__ float g_rowgate[MAXROWS];
__device__ int   g_perm[MAXROWS];
__device__ int   g_topidx[MAXROWS];
__device__ float g_gatesv[MAXROWS];
__device__ float g_imp_part[NE*NT];
__device__ float g_load_part[NE*NT];
__device__ float g_impsum[NE];
__device__ float g_loadsum[NE];
__device__ int   g_tile_e[MAXTILES];
__device__ int   g_tile_r0[MAXTILES];
__device__ int   g_tile_r1[MAXTILES];
__device__ int   g_ntiles;
__device__ int   g_fin;
__device__ float g_wgT[NE*DM];                     // [e][k] transposed gate weights
__device__ float g_wnT[NE*DM];
__device__ __half g_Xrh[(size_t)NT * DM];          // 8 MB,  K-perm16 fp16 x
__device__ __half g_Hh[(size_t)MAXROWS * DF];      // 32 MB, K-perm16 fp16 H
__device__ __half g_w1th[(size_t)NE * DF * DM];    // 32 MB [E][N=DF][K=DM] perm16
__device__ __half g_w2th[(size_t)NE * DM * DF];    // 32 MB [E][N=DM][K=DF] perm16

// ---------------- helpers ----------------
__device__ __forceinline__ uint32_t smem_u32(const void* p) {
    uint32_t r;
    asm("{ .reg .u64 t; cvta.to.shared.u64 t, %1; cvt.u32.u64 %0, t; }" : "=r"(r) : "l"(p));
    return r;
}
// within each 16-group, memory order [0,1,8,9, 2,3,10,11, 4,5,12,13, 6,7,14,15]
__device__ __forceinline__ int permk16(int k) {
    int r = k & 15, m = r & 7, h = (r >> 3) & 1;
    return (k & ~15) + (m >> 1) * 4 + h * 2 + (m & 1);
}
__device__ __forceinline__ void mma_f16(float* c, uint32_t a0, uint32_t a1,
                                        uint32_t a2, uint32_t a3,
                                        uint32_t b0, uint32_t b1) {
    asm volatile("mma.sync.aligned.m16n8k16.row.col.f32.f16.f16.f32 "
        "{%0,%1,%2,%3}, {%4,%5,%6,%7}, {%8,%9}, {%0,%1,%2,%3};"
        : "+f"(c[0]), "+f"(c[1]), "+f"(c[2]), "+f"(c[3])
        : "r"(a0), "r"(a1), "r"(a2), "r"(a3), "r"(b0), "r"(b1));
}

// ---------------- reset + gate-weight transpose ----------------
__global__ void reset_kernel(const float* __restrict__ wg, const float* __restrict__ wn) {
    int j = blockIdx.x * 256 + threadIdx.x;      // 0..8191
    int e = j >> 10, k = j & 1023;
    g_wgT[j] = wg[k * NE + e];
    g_wnT[j] = wn[k * NE + e];
    if (blockIdx.x == 0 && threadIdx.x < NE) g_counts[threadIdx.x] = 0;
    if (blockIdx.x == 0 && threadIdx.x == NE) g_fin = 0;
}

// ---------------- gating: one warp per token; coalesced [e][k] weight reads ----------
__global__ void gating_kernel(const float* __restrict__ x,
                              const float* __restrict__ noise)
{
    int warp = (blockIdx.x * blockDim.x + threadIdx.x) >> 5;
    int lane = threadIdx.x & 31;
    if (warp >= NT) return;
    const int t = warp;

    float cg[NE], ng[NE];
    #pragma unroll
    for (int e = 0; e < NE; e++) { cg[e] = 0.f; ng[e] = 0.f; }

    const float* xr = x + (size_t)t * DM;
    __half* xo = g_Xrh + (size_t)t * DM;
    for (int k = lane; k < DM; k += 32) {
        float xv = xr[k];
        xo[permk16(k)] = __float2half_rn(xv);
        #pragma unroll
        for (int e = 0; e < NE; e++) {
            cg[e] = fmaf(xv, g_wgT[e * DM + k], cg[e]);
            ng[e] = fmaf(xv, g_wnT[e * DM + k], ng[e]);
        }
    }
    #pragma unroll
    for (int e = 0; e < NE; e++) {
        #pragma unroll
        for (int o = 16; o > 0; o >>= 1) {
            cg[e] += __shfl_xor_sync(0xFFFFFFFFu, cg[e], o);
            ng[e] += __shfl_xor_sync(0xFFFFFFFFu, ng[e], o);
        }
    }

    if (lane == 0) {
        float clean[NE], stdv[NE], noisy[NE];
        #pragma unroll
        for (int e = 0; e < NE; e++) {
            clean[e] = cg[e];
            float v = ng[e];
            float sp = fmaxf(v, 0.f) + log1pf(expf(-fabsf(v)));
            stdv[e]  = sp + 0.01f;
            noisy[e] = clean[e] + noise[(size_t)t * NE + e] * stdv[e];
        }
        int i0 = 0, i1 = -1;
        float v0 = -CUDART_INF_F, v1 = -CUDART_INF_F, v2 = -CUDART_INF_F;
        #pragma unroll
        for (int e = 0; e < NE; e++) if (noisy[e] > v0) { v0 = noisy[e]; i0 = e; }
        #pragma unroll
        for (int e = 0; e < NE; e++) if (e != i0 && noisy[e] > v1) { v1 = noisy[e]; i1 = e; }
        #pragma unroll
        for (int e = 0; e < NE; e++) if (e != i0 && e != i1 && noisy[e] > v2) v2 = noisy[e];

        float d = expf(v1 - v0);
        float g0 = 1.f / (1.f + d);
        float g1 = d / (1.f + d);

        g_topidx[2*t]   = i0;  g_topidx[2*t+1] = i1;
        g_gatesv[2*t]   = g0;  g_gatesv[2*t+1] = g1;
        atomicAdd(&g_counts[i0], 1);
        atomicAdd(&g_counts[i1], 1);

        #pragma unroll
        for (int e = 0; e < NE; e++) {
            bool is_in = noisy[e] > v2;
            float thr  = is_in ? v2 : v1;
            float p = normcdff((clean[e] - thr) / stdv[e]);
            g_load_part[e*NT + t] = p;
            g_imp_part[e*NT + t]  = (e == i0) ? g0 : ((e == i1) ? g1 : 0.f);
        }
    }
}

// ---------------- merged meta + scatter: one block of 256 ----------------
__global__ void scatter_meta_kernel() {
    __shared__ int soff[NE];
    __shared__ int scur[NE];
    const int tid = threadIdx.x;
    if (tid == 0) {
        int off = 0, nt = 0;
        for (int e = 0; e < NE; e++) {
            soff[e] = off;
            int c = g_counts[e];
            for (int r = 0; r < c; r += 128) {
                g_tile_e[nt]  = e;
                g_tile_r0[nt] = off + r;
                g_tile_r1[nt] = off + ((r + 128 < c) ? (r + 128) : c);
                nt++;
            }
            off += c;
        }
        g_ntiles = nt;
    }
    if (tid < NE) scur[tid] = 0;
    __syncthreads();
    for (int t = tid; t < NT; t += 256) {
        #pragma unroll
        for (int j = 0; j < 2; j++) {
            int e = g_topidx[2*t + j];
            int p = atomicAdd(&scur[e], 1);
            int row = soff[e] + p;
            g_perm[row]    = t;
            g_rowgate[row] = g_gatesv[2*t + j];
        }
    }
}

// ---------------- w1 transpose -> fp16 perm16 (standalone; FFN1 needs it) ----------
__global__ void transpose_w1_kernel(const float* __restrict__ W1) {
    __shared__ float t[32][33];
    const int e = blockIdx.z;
    const float* Wp = W1 + (size_t)e * DM * DF;
    __half* Wo = g_w1th + (size_t)e * DM * DF;
    const int n0 = blockIdx.x * 32;   // N = DF, 64 blocks
    const int k0 = blockIdx.y * 32;   // K = DM, 32 blocks
    int tx = threadIdx.x, ty = threadIdx.y;
    #pragma unroll
    for (int i = 0; i < 32; i += 8)
        t[ty + i][tx] = Wp[(size_t)(k0 + ty + i) * DF + n0 + tx];
    __syncthreads();
    #pragma unroll
    for (int i = 0; i < 32; i += 8)
        Wo[(size_t)(n0 + ty + i) * DM + permk16(k0 + tx)] = __float2half_rn(t[tx][ty + i]);
}

// ---------------- fp16 mma.sync grouped GEMM (R8-proven config) ----------------
// FFN1 blocks additionally repack their share (~14 tiles each) of
// W2[e][K=2048][N=1024] -> g_w2th[e][n][K-perm16] AFTER the GEMM epilogue,
// reusing the freed smem. DRAM-bound transpose overlaps GEMM wave tail.
#define RSH 80
#define ASTH (128*RSH)
#define STFH (2*ASTH)
#define GEMM_SMEM (2 * STFH * 2)       // 81920 bytes

template<bool FFN1>
__global__ void __launch_bounds__(256, 2)
mma_ffn_kernel(const float* __restrict__ bias, float* __restrict__ out,
               const float* __restrict__ W2src)
{
    constexpr int KTOT = FFN1 ? DM : DF;
    constexpr int NTOT = FFN1 ? DF : DM;
    constexpr int NS   = KTOT / 64;

    extern __shared__ __half smh[];
    const uint32_t smb = smem_u32(smh);
    const int tid = threadIdx.x;

    const int tile = blockIdx.y;
    const bool do_gemm = tile < g_ntiles;

    if (do_gemm) {
        const int e  = g_tile_e[tile];
        const int r0 = g_tile_r0[tile];
        const int r1 = g_tile_r1[tile];
        const int n0 = blockIdx.x * 128;

        const __half* Abase = FFN1 ? g_Xrh : g_Hh;
        const __half* Wt    = FFN1 ? g_w1th : g_w2th;

        const int wid = tid >> 5;
        const int lane = tid & 31;
        const int warp_m = wid >> 2;   // 0..1
        const int warp_n = wid & 3;    // 0..3
        const int lm = lane >> 2;      // 0..7
        const int lk = lane & 3;       // 0..3

        const __half* src[8]; uint32_t sz[8]; uint32_t dst[8];
        #pragma unroll
        for (int i = 0; i < 8; i++) {
            int idx = tid + i * 256;
            if (idx < 1024) {
                int row = idx >> 3, ch = idx & 7;
                int gr = r0 + row;
                bool v = gr < r1;
                size_t ar = FFN1 ? (v ? (size_t)g_perm[gr] : 0) : (v ? (size_t)gr : 0);
                src[i] = Abase + ar * KTOT + ch * 8;
                sz[i]  = v ? 16u : 0u;
                dst[i] = smb + (uint32_t)(row * RSH + ch * 8) * 2u;
            } else {
                int j = idx - 1024;
                int row = j >> 3, ch = j & 7;
                src[i] = Wt + ((size_t)e * NTOT + (size_t)(n0 + row)) * KTOT + ch * 8;
                sz[i]  = 16u;
                dst[i] = smb + (uint32_t)(ASTH + row * RSH + ch * 8) * 2u;
            }
        }

        float acc[4][4][4];
        #pragma unroll
        for (int a = 0; a < 4; a++)
            #pragma unroll
            for (int b = 0; b < 4; b++)
                #pragma unroll
                for (int c = 0; c < 4; c++) acc[a][b][c] = 0.f;

        #pragma unroll
        for (int i = 0; i < 8; i++)
            asm volatile("cp.async.cg.shared.global [%0], [%1], 16, %2;"
                         :: "r"(dst[i]), "l"(src[i]), "r"(sz[i]) : "memory");
        asm volatile("cp.async.commit_group;" ::: "memory");

        for (int s = 0; s < NS; s++) {
            asm volatile("cp.async.wait_group 0;" ::: "memory");
            __syncthreads();

            if (s + 1 < NS) {
                uint32_t so = (uint32_t)(((s + 1) & 1) * STFH * 2);
                int k0 = (s + 1) * 64;
                #pragma unroll
                for (int i = 0; i < 8; i++)
                    asm volatile("cp.async.cg.shared.global [%0], [%1], 16, %2;"
                                 :: "r"(dst[i] + so), "l"(src[i] + k0), "r"(sz[i]) : "memory");
                asm volatile("cp.async.commit_group;" ::: "memory");
            }

            const __half* A = smh + (s & 1) * STFH;
            const __half* B = A + ASTH;

            #pragma unroll
            for (int kk = 0; kk < 4; kk++) {
                const int ko = kk * 16 + lk * 4;
                uint32_t af[4][4], bf[4][2];
                #pragma unroll
                for (int mt = 0; mt < 4; mt++) {
                    int r = warp_m * 64 + mt * 16 + lm;
                    uint2 p0 = *(const uint2*)(A + r * RSH + ko);
                    uint2 p1 = *(const uint2*)(A + (r + 8) * RSH + ko);
                    af[mt][0] = p0.x; af[mt][2] = p0.y;
                    af[mt][1] = p1.x; af[mt][3] = p1.y;
                }
                #pragma unroll
                for (int nt = 0; nt < 4; nt++) {
                    int c = warp_n * 32 + nt * 8 + lm;
                    uint2 pb = *(const uint2*)(B + c * RSH + ko);
                    bf[nt][0] = pb.x; bf[nt][1] = pb.y;
                }
                #pragma unroll
                for (int mt = 0; mt < 4; mt++)
                    #pragma unroll
                    for (int nt = 0; nt < 4; nt++)
                        mma_f16(acc[mt][nt], af[mt][0], af[mt][1], af[mt][2], af[mt][3],
                                bf[nt][0], bf[nt][1]);
            }
        }

        // ---- epilogue ----
        #pragma unroll
        for (int mt = 0; mt < 4; mt++) {
            #pragma unroll
            for (int nt = 0; nt < 4; nt++) {
                int c0 = n0 + warp_n * 32 + nt * 8 + 2 * lk;   // even
                float b0 = bias[(size_t)e * NTOT + c0];
                float b1 = bias[(size_t)e * NTOT + c0 + 1];
                #pragma unroll
                for (int h = 0; h < 2; h++) {
                    int row = warp_m * 64 + mt * 16 + lm + h * 8;
                    int gr = r0 + row;
                    if (gr >= r1) continue;
                    float v0 = acc[mt][nt][2*h + 0] + b0;
                    float v1 = acc[mt][nt][2*h + 1] + b1;
                    if (FFN1) {
                        int m = c0 & 7, hb = (c0 >> 3) & 1;
                        int pos = (c0 & ~15) + (m >> 1) * 4 + hb * 2;
                        __half2 hv = __floats2half2_rn(fmaxf(v0, 0.f), fmaxf(v1, 0.f));
                        *(__half2*)(g_Hh + (size_t)gr * DF + pos) = hv;
                    } else {
                        float gate = g_rowgate[gr];
                        float* o = out + (size_t)g_perm[gr] * DM;
                        atomicAdd(o + c0,     v0 * gate);
                        atomicAdd(o + c0 + 1, v1 * gate);
                    }
                }
            }
        }
    }

    // ---- FFN1 only: this block's share of the w2 transpose (smem reuse) ----
    if (FFN1) {
        float (*tb)[33] = (float(*)[33])smh;
        const int bid = blockIdx.y * 16 + blockIdx.x;    // 0..1151
        const int tx = tid & 31, ty = tid >> 5;          // 32 x 8
        for (int j = bid; j < W2TILES; j += FFN1_BLOCKS) {
            __syncthreads();
            const int e2 = j >> 11;
            const int rem = j & 2047;
            const int kb = rem & 63;       // K = 2048 -> 64 tiles
            const int nb = rem >> 6;       // N = 1024 -> 32 tiles
            const int k0 = kb * 32, n0t = nb * 32;
            const float* Wp = W2src + (size_t)e2 * DF * DM;
            __half* Wo = g_w2th + (size_t)e2 * DF * DM;
            #pragma unroll
            for (int i = 0; i < 32; i += 8)
                tb[ty + i][tx] = Wp[(size_t)(k0 + ty + i) * DM + n0t + tx];
            __syncthreads();
            #pragma unroll
            for (int i = 0; i < 32; i += 8)
                Wo[(size_t)(n0t + ty + i) * DF + permk16(k0 + tx)] =
                    __float2half_rn(tb[tx][ty + i]);
        }
    }
}

// ---------------- finish: eps fixup + loss reduction + loss (fused) ----------------
__global__ void finish_kernel(float* __restrict__ out, int out_size) {
    int idx = blockIdx.x * blockDim.x + threadIdx.x;
    float v = out[idx];
    if (v == 0.0f) out[idx] = 2.2204460492503131e-16f;

    if (blockIdx.x < NE) {
        const int e = blockIdx.x;
        __shared__ float sl[256], si[256];
        float a = 0.f, b = 0.f;
        for (int i = threadIdx.x; i < NT; i += 256) {
            a += g_load_part[e*NT + i];
            b += g_imp_part[e*NT + i];
        }
        sl[threadIdx.x] = a; si[threadIdx.x] = b;
        __syncthreads();
        for (int s = 128; s > 0; s >>= 1) {
            if (threadIdx.x < s) {
                sl[threadIdx.x] += sl[threadIdx.x + s];
                si[threadIdx.x] += si[threadIdx.x + s];
            }
            __syncthreads();
        }
        if (threadIdx.x == 0) {
            g_loadsum[e] = sl[0];
            g_impsum[e]  = si[0];
            __threadfence();
            if (atomicAdd(&g_fin, 1) == NE - 1) {
                __threadfence();
                float mi = 0.f, ml = 0.f;
                for (int k = 0; k < NE; k++) { mi += g_impsum[k]; ml += g_loadsum[k]; }
                mi *= (1.f / NE); ml *= (1.f / NE);
                float vi = 0.f, vl = 0.f;
                for (int k = 0; k < NE; k++) {
                    float di = g_impsum[k] - mi; vi += di * di;
                    float dl = g_loadsum[k] - ml; vl += dl * dl;
                }
                vi /= (float)(NE - 1);
                vl /= (float)(NE - 1);
                out[out_size - 1] = 0.1f * (vi / (mi*mi + 1e-10f) + vl / (ml*ml + 1e-10f));
            }
        }
    }
}

// ---------------- launch ----------------
extern "C" void kernel_launch(void* const* d_in, const int* in_sizes, int n_in,
                              void* d_out, int out_size) {
    const float* x     = (const float*)d_in[0];
    const float* noise = (const float*)d_in[1];
    const float* wg    = (const float*)d_in[2];
    const float* wn    = (const float*)d_in[3];
    const float* w1    = (const float*)d_in[4];
    const float* b1    = (const float*)d_in[5];
    const float* w2    = (const float*)d_in[6];
    const float* b2    = (const float*)d_in[7];
    float* out = (float*)d_out;

    cudaFuncSetAttribute(mma_ffn_kernel<true>,
                         cudaFuncAttributeMaxDynamicSharedMemorySize, GEMM_SMEM);
    cudaFuncSetAttribute(mma_ffn_kernel<false>,
                         cudaFuncAttributeMaxDynamicSharedMemorySize, GEMM_SMEM);

    cudaMemsetAsync(out, 0, (size_t)out_size * sizeof(float));
    reset_kernel<<<32, 256>>>(wg, wn);
    gating_kernel<<<NT/4, 128>>>(x, noise);
    scatter_meta_kernel<<<1, 256>>>();

    transpose_w1_kernel<<<dim3(64, 32, NE), dim3(32, 8)>>>(w1);

    // FFN1 GEMM + embedded w2 transpose (post-epilogue, smem reuse)
    mma_ffn_kernel<true ><<<dim3(16, TILEY), 256, GEMM_SMEM>>>(b1, nullptr, w2);
    mma_ffn_kernel<false><<<dim3(DM/128, TILEY), 256, GEMM_SMEM>>>(b2, out, nullptr);

    finish_kernel<<<(NT*DM)/256, 256>>>(out, out_size);
}

// round 17
// speedup vs baseline: 1.0615x; 1.0044x over previous
#include <cuda_runtime.h>
#include <cuda_fp16.h>
#include <math.h>
#include <math_constants.h>
#include <stdint.h>

#define NT 4096
#define DM 1024
#define DF 2048
#define NE 8
#define MAXROWS (2*NT)
#define MAXTILES 80
#define TILEY 72

// ---------------- static device scratch ----------------
__device__ int   g_counts[NE];
__device__ float g_rowgate[MAXROWS];
__device__ int   g_perm[MAXROWS];
__device__ int   g_topidx[MAXROWS];
__device__ float g_gatesv[MAXROWS];
__device__ float g_imp_part[NE*NT];
__device__ float g_load_part[NE*NT];
__device__ float g_impsum[NE];
__device__ float g_loadsum[NE];
__device__ int   g_tile_e[MAXTILES];
__device__ int   g_tile_r0[MAXTILES];
__device__ int   g_tile_r1[MAXTILES];
__device__ int   g_ntiles;
__device__ int   g_fin;
__device__ float g_wgT[NE*DM];                     // [e][k] transposed gate weights
__device__ float g_wnT[NE*DM];
__device__ __half g_Xrh[(size_t)NT * DM];          // 8 MB,  K-perm16 fp16 x
__device__ __half g_Hh[(size_t)MAXROWS * DF];      // 32 MB, K-perm16 fp16 H
__device__ __half g_w1th[(size_t)NE * DF * DM];    // 32 MB [E][N=DF][K=DM] perm16
__device__ __half g_w2th[(size_t)NE * DM * DF];    // 32 MB [E][N=DM][K=DF] perm16

// ---------------- helpers ----------------
__device__ __forceinline__ uint32_t smem_u32(const void* p) {
    uint32_t r;
    asm("{ .reg .u64 t; cvta.to.shared.u64 t, %1; cvt.u32.u64 %0, t; }" : "=r"(r) : "l"(p));
    return r;
}
// within each 16-group, memory order [0,1,8,9, 2,3,10,11, 4,5,12,13, 6,7,14,15]
__device__ __forceinline__ int permk16(int k) {
    int r = k & 15, m = r & 7, h = (r >> 3) & 1;
    return (k & ~15) + (m >> 1) * 4 + h * 2 + (m & 1);
}
__device__ __forceinline__ void mma_f16(float* c, uint32_t a0, uint32_t a1,
                                        uint32_t a2, uint32_t a3,
                                        uint32_t b0, uint32_t b1) {
    asm volatile("mma.sync.aligned.m16n8k16.row.col.f32.f16.f16.f32 "
        "{%0,%1,%2,%3}, {%4,%5,%6,%7}, {%8,%9}, {%0,%1,%2,%3};"
        : "+f"(c[0]), "+f"(c[1]), "+f"(c[2]), "+f"(c[3])
        : "r"(a0), "r"(a1), "r"(a2), "r"(a3), "r"(b0), "r"(b1));
}

// ---------------- reset + gate-weight transpose ----------------
__global__ void reset_kernel(const float* __restrict__ wg, const float* __restrict__ wn) {
    int j = blockIdx.x * 256 + threadIdx.x;      // 0..8191
    int e = j >> 10, k = j & 1023;
    g_wgT[j] = wg[k * NE + e];
    g_wnT[j] = wn[k * NE + e];
    if (blockIdx.x == 0 && threadIdx.x < NE) g_counts[threadIdx.x] = 0;
    if (blockIdx.x == 0 && threadIdx.x == NE) g_fin = 0;
}

// ---------------- gating: one warp per token; coalesced [e][k] weight reads ----------
__global__ void gating_kernel(const float* __restrict__ x,
                              const float* __restrict__ noise)
{
    int warp = (blockIdx.x * blockDim.x + threadIdx.x) >> 5;
    int lane = threadIdx.x & 31;
    if (warp >= NT) return;
    const int t = warp;

    float cg[NE], ng[NE];
    #pragma unroll
    for (int e = 0; e < NE; e++) { cg[e] = 0.f; ng[e] = 0.f; }

    const float* xr = x + (size_t)t * DM;
    __half* xo = g_Xrh + (size_t)t * DM;
    for (int k = lane; k < DM; k += 32) {
        float xv = xr[k];
        xo[permk16(k)] = __float2half_rn(xv);
        #pragma unroll
        for (int e = 0; e < NE; e++) {
            cg[e] = fmaf(xv, g_wgT[e * DM + k], cg[e]);
            ng[e] = fmaf(xv, g_wnT[e * DM + k], ng[e]);
        }
    }
    #pragma unroll
    for (int e = 0; e < NE; e++) {
        #pragma unroll
        for (int o = 16; o > 0; o >>= 1) {
            cg[e] += __shfl_xor_sync(0xFFFFFFFFu, cg[e], o);
            ng[e] += __shfl_xor_sync(0xFFFFFFFFu, ng[e], o);
        }
    }

    if (lane == 0) {
        float clean[NE], stdv[NE], noisy[NE];
        #pragma unroll
        for (int e = 0; e < NE; e++) {
            clean[e] = cg[e];
            float v = ng[e];
            float sp = fmaxf(v, 0.f) + log1pf(expf(-fabsf(v)));
            stdv[e]  = sp + 0.01f;
            noisy[e] = clean[e] + noise[(size_t)t * NE + e] * stdv[e];
        }
        int i0 = 0, i1 = -1;
        float v0 = -CUDART_INF_F, v1 = -CUDART_INF_F, v2 = -CUDART_INF_F;
        #pragma unroll
        for (int e = 0; e < NE; e++) if (noisy[e] > v0) { v0 = noisy[e]; i0 = e; }
        #pragma unroll
        for (int e = 0; e < NE; e++) if (e != i0 && noisy[e] > v1) { v1 = noisy[e]; i1 = e; }
        #pragma unroll
        for (int e = 0; e < NE; e++) if (e != i0 && e != i1 && noisy[e] > v2) v2 = noisy[e];

        float d = expf(v1 - v0);
        float g0 = 1.f / (1.f + d);
        float g1 = d / (1.f + d);

        g_topidx[2*t]   = i0;  g_topidx[2*t+1] = i1;
        g_gatesv[2*t]   = g0;  g_gatesv[2*t+1] = g1;
        atomicAdd(&g_counts[i0], 1);
        atomicAdd(&g_counts[i1], 1);

        #pragma unroll
        for (int e = 0; e < NE; e++) {
            bool is_in = noisy[e] > v2;
            float thr  = is_in ? v2 : v1;
            float p = normcdff((clean[e] - thr) / stdv[e]);
            g_load_part[e*NT + t] = p;
            g_imp_part[e*NT + t]  = (e == i0) ? g0 : ((e == i1) ? g1 : 0.f);
        }
    }
}

// ---------------- merged meta + scatter: one block of 256 ----------------
__global__ void scatter_meta_kernel() {
    __shared__ int soff[NE];
    __shared__ int scur[NE];
    const int tid = threadIdx.x;
    if (tid == 0) {
        int off = 0, nt = 0;
        for (int e = 0; e < NE; e++) {
            soff[e] = off;
            int c = g_counts[e];
            for (int r = 0; r < c; r += 128) {
                g_tile_e[nt]  = e;
                g_tile_r0[nt] = off + r;
                g_tile_r1[nt] = off + ((r + 128 < c) ? (r + 128) : c);
                nt++;
            }
            off += c;
        }
        g_ntiles = nt;
    }
    if (tid < NE) scur[tid] = 0;
    __syncthreads();
    for (int t = tid; t < NT; t += 256) {
        #pragma unroll
        for (int j = 0; j < 2; j++) {
            int e = g_topidx[2*t + j];
            int p = atomicAdd(&scur[e], 1);
            int row = soff[e] + p;
            g_perm[row]    = t;
            g_rowgate[row] = g_gatesv[2*t + j];
        }
    }
}

// ---------------- merged vectorized weight transpose -> fp16 perm16 ----------------
// grid (2048, 16): y = layer (0..7 w1, 8..15 w2), x = 32x32 tile index.
// Load: one LDG.128 per thread. Store: two STG.32 (__half2; permk16 even pairs adjacent).
__global__ void __launch_bounds__(256)
transpose_h_kernel(const float* __restrict__ W1, const float* __restrict__ W2)
{
    __shared__ float t[32][33];
    const int z = blockIdx.y;
    const bool one = z < 8;
    const int e = one ? z : (z - 8);
    const int K = one ? DM : DF;
    const int N = one ? DF : DM;
    const int ntile = N >> 5;
    const int kb = blockIdx.x / ntile;
    const int nb = blockIdx.x - kb * ntile;
    const int k0 = kb * 32, n0 = nb * 32;
    const float* Wp = (one ? W1 : W2) + (size_t)e * K * N;
    __half* Wo = (one ? g_w1th : g_w2th) + (size_t)e * K * N;
    const int tid = threadIdx.x;

    {   // load 32x32 tile: thread -> (k-row tid>>3, n-col quad (tid&7)*4)
        int r = tid >> 3, c4 = (tid & 7) * 4;
        float4 v = *(const float4*)(Wp + (size_t)(k0 + r) * N + n0 + c4);
        t[r][c4] = v.x; t[r][c4+1] = v.y; t[r][c4+2] = v.z; t[r][c4+3] = v.w;
    }
    __syncthreads();
    {   // write: thread -> (n-row tid>>3, k quad (tid&7)*4); even k pairs -> half2
        int nr = tid >> 3, kp = (tid & 7) * 4;
        __half* orow = Wo + (size_t)(n0 + nr) * K;
        #pragma unroll
        for (int q = 0; q < 2; q++) {
            int k = kp + 2 * q;
            __half2 hv = __floats2half2_rn(t[k][nr], t[k+1][nr]);
            *(__half2*)(orow + permk16(k0 + k)) = hv;
        }
    }
}

// ---------------- fp16 mma.sync grouped GEMM (R8/R14-proven config) ----------------
#define RSH 80
#define ASTH (128*RSH)
#define STFH (2*ASTH)
#define GEMM_SMEM (2 * STFH * 2)       // 81920 bytes

template<bool FFN1>
__global__ void __launch_bounds__(256, 2)
mma_ffn_kernel(const float* __restrict__ bias, float* __restrict__ out)
{
    constexpr int KTOT = FFN1 ? DM : DF;
    constexpr int NTOT = FFN1 ? DF : DM;
    constexpr int NS   = KTOT / 64;

    int tile = blockIdx.y;
    if (tile >= g_ntiles) return;
    const int e  = g_tile_e[tile];
    const int r0 = g_tile_r0[tile];
    const int r1 = g_tile_r1[tile];
    const int n0 = blockIdx.x * 128;

    const __half* Abase = FFN1 ? g_Xrh : g_Hh;
    const __half* Wt    = FFN1 ? g_w1th : g_w2th;

    extern __shared__ __half smh[];
    const uint32_t smb = smem_u32(smh);

    const int tid = threadIdx.x;
    const int wid = tid >> 5;
    const int lane = tid & 31;
    const int warp_m = wid >> 2;   // 0..1
    const int warp_n = wid & 3;    // 0..3
    const int lm = lane >> 2;      // 0..7
    const int lk = lane & 3;       // 0..3

    const __half* src[8]; uint32_t sz[8]; uint32_t dst[8];
    #pragma unroll
    for (int i = 0; i < 8; i++) {
        int idx = tid + i * 256;
        if (idx < 1024) {
            int row = idx >> 3, ch = idx & 7;
            int gr = r0 + row;
            bool v = gr < r1;
            size_t ar = FFN1 ? (v ? (size_t)g_perm[gr] : 0) : (v ? (size_t)gr : 0);
            src[i] = Abase + ar * KTOT + ch * 8;
            sz[i]  = v ? 16u : 0u;
            dst[i] = smb + (uint32_t)(row * RSH + ch * 8) * 2u;
        } else {
            int j = idx - 1024;
            int row = j >> 3, ch = j & 7;
            src[i] = Wt + ((size_t)e * NTOT + (size_t)(n0 + row)) * KTOT + ch * 8;
            sz[i]  = 16u;
            dst[i] = smb + (uint32_t)(ASTH + row * RSH + ch * 8) * 2u;
        }
    }

    float acc[4][4][4];
    #pragma unroll
    for (int a = 0; a < 4; a++)
        #pragma unroll
        for (int b = 0; b < 4; b++)
            #pragma unroll
            for (int c = 0; c < 4; c++) acc[a][b][c] = 0.f;

    #pragma unroll
    for (int i = 0; i < 8; i++)
        asm volatile("cp.async.cg.shared.global [%0], [%1], 16, %2;"
                     :: "r"(dst[i]), "l"(src[i]), "r"(sz[i]) : "memory");
    asm volatile("cp.async.commit_group;" ::: "memory");

    for (int s = 0; s < NS; s++) {
        asm volatile("cp.async.wait_group 0;" ::: "memory");
        __syncthreads();

        if (s + 1 < NS) {
            uint32_t so = (uint32_t)(((s + 1) & 1) * STFH * 2);
            int k0 = (s + 1) * 64;
            #pragma unroll
            for (int i = 0; i < 8; i++)
                asm volatile("cp.async.cg.shared.global [%0], [%1], 16, %2;"
                             :: "r"(dst[i] + so), "l"(src[i] + k0), "r"(sz[i]) : "memory");
            asm volatile("cp.async.commit_group;" ::: "memory");
        }

        const __half* A = smh + (s & 1) * STFH;
        const __half* B = A + ASTH;

        #pragma unroll
        for (int kk = 0; kk < 4; kk++) {
            const int ko = kk * 16 + lk * 4;
            uint32_t af[4][4], bf[4][2];
            #pragma unroll
            for (int mt = 0; mt < 4; mt++) {
                int r = warp_m * 64 + mt * 16 + lm;
                uint2 p0 = *(const uint2*)(A + r * RSH + ko);
                uint2 p1 = *(const uint2*)(A + (r + 8) * RSH + ko);
                af[mt][0] = p0.x; af[mt][2] = p0.y;
                af[mt][1] = p1.x; af[mt][3] = p1.y;
            }
            #pragma unroll
            for (int nt = 0; nt < 4; nt++) {
                int c = warp_n * 32 + nt * 8 + lm;
                uint2 pb = *(const uint2*)(B + c * RSH + ko);
                bf[nt][0] = pb.x; bf[nt][1] = pb.y;
            }
            #pragma unroll
            for (int mt = 0; mt < 4; mt++)
                #pragma unroll
                for (int nt = 0; nt < 4; nt++)
                    mma_f16(acc[mt][nt], af[mt][0], af[mt][1], af[mt][2], af[mt][3],
                            bf[nt][0], bf[nt][1]);
        }
    }

    // ---- epilogue ----
    #pragma unroll
    for (int mt = 0; mt < 4; mt++) {
        #pragma unroll
        for (int nt = 0; nt < 4; nt++) {
            int c0 = n0 + warp_n * 32 + nt * 8 + 2 * lk;   // even
            float b0 = bias[(size_t)e * NTOT + c0];
            float b1 = bias[(size_t)e * NTOT + c0 + 1];
            #pragma unroll
            for (int h = 0; h < 2; h++) {
                int row = warp_m * 64 + mt * 16 + lm + h * 8;
                int gr = r0 + row;
                if (gr >= r1) continue;
                float v0 = acc[mt][nt][2*h + 0] + b0;
                float v1 = acc[mt][nt][2*h + 1] + b1;
                if (FFN1) {
                    int m = c0 & 7, hb = (c0 >> 3) & 1;
                    int pos = (c0 & ~15) + (m >> 1) * 4 + hb * 2;
                    __half2 hv = __floats2half2_rn(fmaxf(v0, 0.f), fmaxf(v1, 0.f));
                    *(__half2*)(g_Hh + (size_t)gr * DF + pos) = hv;
                } else {
                    float gate = g_rowgate[gr];
                    float* o = out + (size_t)g_perm[gr] * DM;
                    atomicAdd(o + c0,     v0 * gate);
                    atomicAdd(o + c0 + 1, v1 * gate);
                }
            }
        }
    }
}

// ---------------- finish: eps fixup + loss reduction + loss (fused) ----------------
__global__ void finish_kernel(float* __restrict__ out, int out_size) {
    int idx = blockIdx.x * blockDim.x + threadIdx.x;
    float v = out[idx];
    if (v == 0.0f) out[idx] = 2.2204460492503131e-16f;

    if (blockIdx.x < NE) {
        const int e = blockIdx.x;
        __shared__ float sl[256], si[256];
        float a = 0.f, b = 0.f;
        for (int i = threadIdx.x; i < NT; i += 256) {
            a += g_load_part[e*NT + i];
            b += g_imp_part[e*NT + i];
        }
        sl[threadIdx.x] = a; si[threadIdx.x] = b;
        __syncthreads();
        for (int s = 128; s > 0; s >>= 1) {
            if (threadIdx.x < s) {
                sl[threadIdx.x] += sl[threadIdx.x + s];
                si[threadIdx.x] += si[threadIdx.x + s];
            }
            __syncthreads();
        }
        if (threadIdx.x == 0) {
            g_loadsum[e] = sl[0];
            g_impsum[e]  = si[0];
            __threadfence();
            if (atomicAdd(&g_fin, 1) == NE - 1) {
                __threadfence();
                float mi = 0.f, ml = 0.f;
                for (int k = 0; k < NE; k++) { mi += g_impsum[k]; ml += g_loadsum[k]; }
                mi *= (1.f / NE); ml *= (1.f / NE);
                float vi = 0.f, vl = 0.f;
                for (int k = 0; k < NE; k++) {
                    float di = g_impsum[k] - mi; vi += di * di;
                    float dl = g_loadsum[k] - ml; vl += dl * dl;
                }
                vi /= (float)(NE - 1);
                vl /= (float)(NE - 1);
                out[out_size - 1] = 0.1f * (vi / (mi*mi + 1e-10f) + vl / (ml*ml + 1e-10f));
            }
        }
    }
}

// ---------------- launch ----------------
extern "C" void kernel_launch(void* const* d_in, const int* in_sizes, int n_in,
                              void* d_out, int out_size) {
    const float* x     = (const float*)d_in[0];
    const float* noise = (const float*)d_in[1];
    const float* wg    = (const float*)d_in[2];
    const float* wn    = (const float*)d_in[3];
    const float* w1    = (const float*)d_in[4];
    const float* b1    = (const float*)d_in[5];
    const float* w2    = (const float*)d_in[6];
    const float* b2    = (const float*)d_in[7];
    float* out = (float*)d_out;

    cudaFuncSetAttribute(mma_ffn_kernel<true>,
                         cudaFuncAttributeMaxDynamicSharedMemorySize, GEMM_SMEM);
    cudaFuncSetAttribute(mma_ffn_kernel<false>,
                         cudaFuncAttributeMaxDynamicSharedMemorySize, GEMM_SMEM);

    cudaMemsetAsync(out, 0, (size_t)out_size * sizeof(float));
    reset_kernel<<<32, 256>>>(wg, wn);
    gating_kernel<<<NT/4, 128>>>(x, noise);
    scatter_meta_kernel<<<1, 256>>>();

    transpose_h_kernel<<<dim3(2048, 16), 256>>>(w1, w2);

    mma_ffn_kernel<true ><<<dim3(DF/128, TILEY), 256, GEMM_SMEM>>>(b1, nullptr);
    mma_ffn_kernel<false><<<dim3(DM/128, TILEY), 256, GEMM_SMEM>>>(b2, out);

    finish_kernel<<<(NT*DM)/256, 256>>>(out, out_size);
}